// round 1
// baseline (speedup 1.0000x reference)
#include <cuda_runtime.h>
#include <cstdint>

#define Hd 1024
#define Fd 2048
#define Td 8192

// ---------------- scratch (allocation-free rule: __device__ globals) ----------
__device__ float g_stats[Td * 2];          // mean, rstd per token
__device__ float g_wts[Td * 4];            // w0, w1, w2, w1+w2 per token
__device__ float g_W1s[2][Hd * Fd];        // s_d-scaled ad_w1 per domain (67? no: 2x8.4MB)
__device__ float g_cvec[2][Fd];            // b_d @ ad_w1 + ad_b1 per domain
__device__ float g_gbuf[(size_t)Td * Fd];  // w1*f_book + w2*f_iwslt (67 MB)

// ---------------- packed f32x2 helpers ---------------------------------------
#define FMA2(acc, a, b) \
    asm("fma.rn.f32x2 %0, %1, %2, %0;" : "+l"(acc) : "l"(a), "l"(b))
#define PACK2(dst, v) \
    asm("mov.b64 %0, {%1, %1};" : "=l"(dst) : "r"(v))

__device__ __forceinline__ float2 unpack2(unsigned long long v) {
    unsigned lo, hi;
    asm("mov.b64 {%0, %1}, %2;" : "=r"(lo), "=r"(hi) : "l"(v));
    return make_float2(__uint_as_float(lo), __uint_as_float(hi));
}

// ---------------- kernel 1: per-token LN stats + gate softmax weights ---------
__global__ void k_gate(const float* __restrict__ x, const int* __restrict__ dm,
                       const float* __restrict__ gw1, const float* __restrict__ gb1,
                       const float* __restrict__ gw2, const float* __restrict__ gb2) {
    const int t = blockIdx.x * 8 + (threadIdx.x >> 5);
    const int lane = threadIdx.x & 31;
    const float* xr = x + (size_t)t * Hd;

    float s = 0.f, ss = 0.f, a0 = 0.f, a1 = 0.f, a2 = 0.f, a3 = 0.f;
    for (int h = lane * 4; h < Hd; h += 128) {
        float4 xv = *(const float4*)(xr + h);
        s  += xv.x + xv.y + xv.z + xv.w;
        ss += xv.x * xv.x + xv.y * xv.y + xv.z * xv.z + xv.w * xv.w;
        const float4* gw = (const float4*)(gw1 + h * 4);  // rows h..h+3 of [H,4]
        float4 w0r = gw[0], w1r = gw[1], w2r = gw[2], w3r = gw[3];
        a0 += xv.x * w0r.x + xv.y * w1r.x + xv.z * w2r.x + xv.w * w3r.x;
        a1 += xv.x * w0r.y + xv.y * w1r.y + xv.z * w2r.y + xv.w * w3r.y;
        a2 += xv.x * w0r.z + xv.y * w1r.z + xv.z * w2r.z + xv.w * w3r.z;
        a3 += xv.x * w0r.w + xv.y * w1r.w + xv.z * w2r.w + xv.w * w3r.w;
    }
    #pragma unroll
    for (int o = 16; o; o >>= 1) {
        s  += __shfl_xor_sync(0xffffffffu, s, o);
        ss += __shfl_xor_sync(0xffffffffu, ss, o);
        a0 += __shfl_xor_sync(0xffffffffu, a0, o);
        a1 += __shfl_xor_sync(0xffffffffu, a1, o);
        a2 += __shfl_xor_sync(0xffffffffu, a2, o);
        a3 += __shfl_xor_sync(0xffffffffu, a3, o);
    }
    if (lane == 0) {
        const float mean = s * (1.f / Hd);
        const float var = ss * (1.f / Hd) - mean * mean;
        g_stats[2 * t] = mean;
        g_stats[2 * t + 1] = rsqrtf(var + 1e-6f);

        float hv[4] = {fmaxf(a0 + gb1[0], 0.f), fmaxf(a1 + gb1[1], 0.f),
                       fmaxf(a2 + gb1[2], 0.f), fmaxf(a3 + gb1[3], 0.f)};
        float lg[4];
        #pragma unroll
        for (int e = 0; e < 4; e++) {
            float acc = gb2[e];
            #pragma unroll
            for (int d = 0; d < 4; d++) acc += hv[d] * gw2[d * 4 + e];
            if (dm[e] == 0) acc = -1e9f;
            lg[e] = acc;
        }
        const float mx = fmaxf(fmaxf(lg[0], lg[1]), fmaxf(lg[2], lg[3]));
        const float e0 = expf(lg[0] - mx), e1 = expf(lg[1] - mx);
        const float e2 = expf(lg[2] - mx), e3 = expf(lg[3] - mx);
        const float inv = 1.f / (e0 + e1 + e2 + e3);
        g_wts[4 * t + 0] = e0 * inv;
        g_wts[4 * t + 1] = e1 * inv;
        g_wts[4 * t + 2] = e2 * inv;
        g_wts[4 * t + 3] = (e1 + e2) * inv;
    }
}

// ---------------- kernel 2a: W1 scaled by LN scale per domain -----------------
__global__ void k_prepw(const float* __restrict__ w1, const float* __restrict__ sb,
                        const float* __restrict__ si) {
    const int i = blockIdx.x * 256 + threadIdx.x;   // over Hd*Fd, exact grid
    const int h = i >> 11;                          // /Fd
    const float w = w1[i];
    g_W1s[0][i] = w * sb[h];
    g_W1s[1][i] = w * si[h];
}

// ---------------- kernel 2b: c_d = b_d @ W1 + ad_b1 ---------------------------
__global__ void k_prepc(const float* __restrict__ w1, const float* __restrict__ bb,
                        const float* __restrict__ bi, const float* __restrict__ ab1) {
    const int i = blockIdx.x * 256 + threadIdx.x;   // 0..2*Fd-1
    const int d = i >> 11;
    const int f = i & (Fd - 1);
    const float* bv = d ? bi : bb;
    float acc = ab1[f];
    #pragma unroll 8
    for (int h = 0; h < Hd; h++) acc = fmaf(__ldg(bv + h), w1[h * Fd + f], acc);
    g_cvec[d][f] = acc;
}

// ---------------- kernel 3: up-proj both domains + relu + weight-combine ------
// C[t,f] = w1[t]*relu(norm(x)[t]·W1s_book[:,f] + cB[f]) + w2[t]*relu(... iwslt)
// tile: 128(M) x 64(N per domain) x 16(K), 256 threads, double buffered
__global__ void __launch_bounds__(256, 2) k_up(const float* __restrict__ x) {
    __shared__ __align__(16) float As[2][16][132];
    __shared__ __align__(16) float Bs[2][2][16][64];
    const int tid = threadIdx.x;
    const int m0 = blockIdx.y * 128;
    const int n0 = blockIdx.x * 64;
    const int ty = tid >> 4, tx = tid & 15;
    const int ar = tid >> 2, ac = (tid & 3) << 2;
    const int br = tid >> 4, bc = (tid & 15) << 2;

    const float m_a = g_stats[2 * (m0 + ar)], r_a = g_stats[2 * (m0 + ar) + 1];
    const float m_b = g_stats[2 * (m0 + ar + 64)], r_b = g_stats[2 * (m0 + ar + 64) + 1];

    const float* aPtr0 = x + (size_t)(m0 + ar) * Hd + ac;
    const float* aPtr1 = x + (size_t)(m0 + ar + 64) * Hd + ac;
    const float* bPtr0 = &g_W1s[0][br * Fd + n0 + bc];
    const float* bPtr1 = &g_W1s[1][br * Fd + n0 + bc];

    float4 aReg0, aReg1, bReg0, bReg1;
    unsigned long long accB[8][2], accI[8][2];
    #pragma unroll
    for (int i = 0; i < 8; i++) {
        accB[i][0] = 0ull; accB[i][1] = 0ull;
        accI[i][0] = 0ull; accI[i][1] = 0ull;
    }

    auto storeTile = [&](int buf) {
        As[buf][ac + 0][ar] = (aReg0.x - m_a) * r_a;
        As[buf][ac + 1][ar] = (aReg0.y - m_a) * r_a;
        As[buf][ac + 2][ar] = (aReg0.z - m_a) * r_a;
        As[buf][ac + 3][ar] = (aReg0.w - m_a) * r_a;
        As[buf][ac + 0][ar + 64] = (aReg1.x - m_b) * r_b;
        As[buf][ac + 1][ar + 64] = (aReg1.y - m_b) * r_b;
        As[buf][ac + 2][ar + 64] = (aReg1.z - m_b) * r_b;
        As[buf][ac + 3][ar + 64] = (aReg1.w - m_b) * r_b;
        *(float4*)&Bs[buf][0][br][bc] = bReg0;
        *(float4*)&Bs[buf][1][br][bc] = bReg1;
    };

    aReg0 = *(const float4*)(aPtr0);
    aReg1 = *(const float4*)(aPtr1);
    bReg0 = *(const float4*)(bPtr0);
    bReg1 = *(const float4*)(bPtr1);
    storeTile(0);
    __syncthreads();

    for (int kt = 0; kt < 64; ++kt) {
        const int buf = kt & 1;
        if (kt < 63) {
            const int k1 = (kt + 1) * 16;
            aReg0 = *(const float4*)(aPtr0 + k1);
            aReg1 = *(const float4*)(aPtr1 + k1);
            bReg0 = *(const float4*)(bPtr0 + (size_t)k1 * Fd);
            bReg1 = *(const float4*)(bPtr1 + (size_t)k1 * Fd);
        }
        #pragma unroll
        for (int kk = 0; kk < 16; ++kk) {
            const uint4 av0 = *(const uint4*)&As[buf][kk][ty * 8];
            const uint4 av1 = *(const uint4*)&As[buf][kk][ty * 8 + 4];
            const unsigned long long bB0 = *(const unsigned long long*)&Bs[buf][0][kk][tx * 4];
            const unsigned long long bB1 = *(const unsigned long long*)&Bs[buf][0][kk][tx * 4 + 2];
            const unsigned long long bI0 = *(const unsigned long long*)&Bs[buf][1][kk][tx * 4];
            const unsigned long long bI1 = *(const unsigned long long*)&Bs[buf][1][kk][tx * 4 + 2];
            const unsigned ai[8] = {av0.x, av0.y, av0.z, av0.w, av1.x, av1.y, av1.z, av1.w};
            #pragma unroll
            for (int i = 0; i < 8; i++) {
                unsigned long long a2;
                PACK2(a2, ai[i]);
                FMA2(accB[i][0], a2, bB0);
                FMA2(accB[i][1], a2, bB1);
                FMA2(accI[i][0], a2, bI0);
                FMA2(accI[i][1], a2, bI1);
            }
        }
        if (kt < 63) storeTile(buf ^ 1);
        __syncthreads();
    }

    const int nb = n0 + tx * 4;
    const float4 cB = *(const float4*)&g_cvec[0][nb];
    const float4 cI = *(const float4*)&g_cvec[1][nb];
    #pragma unroll
    for (int i = 0; i < 8; i++) {
        const int m = m0 + ty * 8 + i;
        const float w1v = g_wts[4 * m + 1], w2v = g_wts[4 * m + 2];
        const float2 pB0 = unpack2(accB[i][0]), pB1 = unpack2(accB[i][1]);
        const float2 pI0 = unpack2(accI[i][0]), pI1 = unpack2(accI[i][1]);
        float4 o;
        o.x = w1v * fmaxf(pB0.x + cB.x, 0.f) + w2v * fmaxf(pI0.x + cI.x, 0.f);
        o.y = w1v * fmaxf(pB0.y + cB.y, 0.f) + w2v * fmaxf(pI0.y + cI.y, 0.f);
        o.z = w1v * fmaxf(pB1.x + cB.z, 0.f) + w2v * fmaxf(pI1.x + cI.z, 0.f);
        o.w = w1v * fmaxf(pB1.y + cB.w, 0.f) + w2v * fmaxf(pI1.y + cI.w, 0.f);
        *(float4*)&g_gbuf[(size_t)m * Fd + nb] = o;
    }
}

// ---------------- kernel 4: down-proj + residual + gated mix ------------------
// out[t,h] = x[t,h]*(1+w0[t]) + g[t,:]·W2[:,h] + (w1+w2)[t]*ad_b2[h]
// tile: 128(M) x 128(N) x 16(K), 256 threads, double buffered
__global__ void __launch_bounds__(256, 2) k_down(const float* __restrict__ x,
                                                 const float* __restrict__ w2,
                                                 const float* __restrict__ b2,
                                                 float* __restrict__ out) {
    __shared__ __align__(16) float As[2][16][132];
    __shared__ __align__(16) float Bs[2][16][128];
    const int tid = threadIdx.x;
    const int m0 = blockIdx.y * 128;
    const int n0 = blockIdx.x * 128;
    const int ty = tid >> 4, tx = tid & 15;
    const int ar = tid >> 2, ac = (tid & 3) << 2;
    const int br0 = tid >> 5, bc0 = (tid & 31) << 2;

    const float* aPtr0 = g_gbuf + (size_t)(m0 + ar) * Fd + ac;
    const float* aPtr1 = g_gbuf + (size_t)(m0 + ar + 64) * Fd + ac;
    const float* bPtr0 = w2 + (size_t)br0 * Hd + n0 + bc0;
    const float* bPtr1 = w2 + (size_t)(br0 + 8) * Hd + n0 + bc0;

    float4 aReg0, aReg1, bReg0, bReg1;
    unsigned long long acc[8][4];
    #pragma unroll
    for (int i = 0; i < 8; i++)
        #pragma unroll
        for (int j = 0; j < 4; j++) acc[i][j] = 0ull;

    auto storeTile = [&](int buf) {
        As[buf][ac + 0][ar] = aReg0.x;
        As[buf][ac + 1][ar] = aReg0.y;
        As[buf][ac + 2][ar] = aReg0.z;
        As[buf][ac + 3][ar] = aReg0.w;
        As[buf][ac + 0][ar + 64] = aReg1.x;
        As[buf][ac + 1][ar + 64] = aReg1.y;
        As[buf][ac + 2][ar + 64] = aReg1.z;
        As[buf][ac + 3][ar + 64] = aReg1.w;
        *(float4*)&Bs[buf][br0][bc0] = bReg0;
        *(float4*)&Bs[buf][br0 + 8][bc0] = bReg1;
    };

    aReg0 = *(const float4*)(aPtr0);
    aReg1 = *(const float4*)(aPtr1);
    bReg0 = *(const float4*)(bPtr0);
    bReg1 = *(const float4*)(bPtr1);
    storeTile(0);
    __syncthreads();

    for (int kt = 0; kt < 128; ++kt) {
        const int buf = kt & 1;
        if (kt < 127) {
            const int k1 = (kt + 1) * 16;
            aReg0 = *(const float4*)(aPtr0 + k1);
            aReg1 = *(const float4*)(aPtr1 + k1);
            bReg0 = *(const float4*)(bPtr0 + (size_t)k1 * Hd);
            bReg1 = *(const float4*)(bPtr1 + (size_t)k1 * Hd);
        }
        #pragma unroll
        for (int kk = 0; kk < 16; ++kk) {
            const uint4 av0 = *(const uint4*)&As[buf][kk][ty * 8];
            const uint4 av1 = *(const uint4*)&As[buf][kk][ty * 8 + 4];
            unsigned long long bv[4];
            bv[0] = *(const unsigned long long*)&Bs[buf][kk][tx * 8];
            bv[1] = *(const unsigned long long*)&Bs[buf][kk][tx * 8 + 2];
            bv[2] = *(const unsigned long long*)&Bs[buf][kk][tx * 8 + 4];
            bv[3] = *(const unsigned long long*)&Bs[buf][kk][tx * 8 + 6];
            const unsigned ai[8] = {av0.x, av0.y, av0.z, av0.w, av1.x, av1.y, av1.z, av1.w};
            #pragma unroll
            for (int i = 0; i < 8; i++) {
                unsigned long long a2;
                PACK2(a2, ai[i]);
                FMA2(acc[i][0], a2, bv[0]);
                FMA2(acc[i][1], a2, bv[1]);
                FMA2(acc[i][2], a2, bv[2]);
                FMA2(acc[i][3], a2, bv[3]);
            }
        }
        if (kt < 127) storeTile(buf ^ 1);
        __syncthreads();
    }

    const int nb = n0 + tx * 8;
    const float4 b2a = *(const float4*)&b2[nb];
    const float4 b2b = *(const float4*)&b2[nb + 4];
    #pragma unroll
    for (int i = 0; i < 8; i++) {
        const int m = m0 + ty * 8 + i;
        const float w0 = g_wts[4 * m];
        const float w12 = g_wts[4 * m + 3];
        const float xs = 1.f + w0;
        const float4 xv0 = *(const float4*)&x[(size_t)m * Hd + nb];
        const float4 xv1 = *(const float4*)&x[(size_t)m * Hd + nb + 4];
        const float2 p0 = unpack2(acc[i][0]), p1 = unpack2(acc[i][1]);
        const float2 p2 = unpack2(acc[i][2]), p3 = unpack2(acc[i][3]);
        float4 o0, o1;
        o0.x = xv0.x * xs + p0.x + w12 * b2a.x;
        o0.y = xv0.y * xs + p0.y + w12 * b2a.y;
        o0.z = xv0.z * xs + p1.x + w12 * b2a.z;
        o0.w = xv0.w * xs + p1.y + w12 * b2a.w;
        o1.x = xv1.x * xs + p2.x + w12 * b2b.x;
        o1.y = xv1.y * xs + p2.y + w12 * b2b.y;
        o1.z = xv1.z * xs + p3.x + w12 * b2b.z;
        o1.w = xv1.w * xs + p3.y + w12 * b2b.w;
        *(float4*)&out[(size_t)m * Hd + nb] = o0;
        *(float4*)&out[(size_t)m * Hd + nb + 4] = o1;
    }
}

// ---------------- launch ------------------------------------------------------
extern "C" void kernel_launch(void* const* d_in, const int* in_sizes, int n_in,
                              void* d_out, int out_size) {
    const float* x   = (const float*)d_in[0];
    const int*   dm  = (const int*)d_in[1];
    const float* gw1 = (const float*)d_in[2];
    const float* gb1 = (const float*)d_in[3];
    const float* gw2 = (const float*)d_in[4];
    const float* gb2 = (const float*)d_in[5];
    const float* sb  = (const float*)d_in[6];
    const float* bb  = (const float*)d_in[7];
    const float* si  = (const float*)d_in[8];
    const float* bi  = (const float*)d_in[9];
    const float* aw1 = (const float*)d_in[10];
    const float* ab1 = (const float*)d_in[11];
    const float* aw2 = (const float*)d_in[12];
    const float* ab2 = (const float*)d_in[13];
    float* out = (float*)d_out;

    k_gate<<<Td / 8, 256>>>(x, dm, gw1, gb1, gw2, gb2);
    k_prepw<<<(Hd * Fd) / 256, 256>>>(aw1, sb, si);
    k_prepc<<<(2 * Fd) / 256, 256>>>(aw1, bb, bi, ab1);
    k_up<<<dim3(Fd / 64, Td / 128), 256>>>(x);
    k_down<<<dim3(Hd / 128, Td / 128), 256>>>(x, aw2, ab2, out);
}

// round 3
// speedup vs baseline: 1.2833x; 1.2833x over previous
#include <cuda_runtime.h>
#include <cuda_bf16.h>
#include <cstdint>

#define Hd 1024
#define Fd 2048
#define Td 8192

// ---------------- scratch (__device__ globals; no allocs allowed) -------------
__device__ __align__(16) float g_stats[Td * 2];   // mean, rstd per token
__device__ __align__(16) float g_wts[Td * 4];     // w0, w1, w2, w1+w2
__device__ __align__(16) float g_cvec[2][Fd];     // b_d @ ad_w1 + ad_b1
__device__ __align__(16) __nv_bfloat16 g_xH[(size_t)Td * Hd];   // norm(x) hi
__device__ __align__(16) __nv_bfloat16 g_xL[(size_t)Td * Hd];   // norm(x) lo
__device__ __align__(16) __nv_bfloat16 g_BbH[(size_t)Fd * Hd];  // W1*s_book^T hi
__device__ __align__(16) __nv_bfloat16 g_BbL[(size_t)Fd * Hd];
__device__ __align__(16) __nv_bfloat16 g_BiH[(size_t)Fd * Hd];  // W1*s_iwslt^T hi
__device__ __align__(16) __nv_bfloat16 g_BiL[(size_t)Fd * Hd];
__device__ __align__(16) __nv_bfloat16 g_W2H[(size_t)Hd * Fd];  // W2^T hi
__device__ __align__(16) __nv_bfloat16 g_W2L[(size_t)Hd * Fd];
__device__ __align__(16) __nv_bfloat16 g_ghi[(size_t)Td * Fd];  // combined act hi
__device__ __align__(16) __nv_bfloat16 g_glo[(size_t)Td * Fd];  // lo

// ---------------- PTX helpers (generic PTX only: no tcgen05) ------------------
__device__ __forceinline__ uint32_t smem_u32(const void* p) {
    uint32_t a;
    asm("{ .reg .u64 t; cvta.to.shared.u64 t, %1; cvt.u32.u64 %0, t; }"
        : "=r"(a) : "l"(p));
    return a;
}
#define CP16(dst, src) \
    asm volatile("cp.async.cg.shared.global [%0], [%1], 16;" \
                 :: "r"(dst), "l"(__cvta_generic_to_global(src)))
#define CP_COMMIT() asm volatile("cp.async.commit_group;" ::: "memory")
#define CP_WAIT0()  asm volatile("cp.async.wait_group 0;" ::: "memory")
#define LDSM4(r, a) \
    asm volatile("ldmatrix.sync.aligned.m8n8.x4.shared.b16 {%0,%1,%2,%3}, [%4];" \
                 : "=r"((r)[0]), "=r"((r)[1]), "=r"((r)[2]), "=r"((r)[3]) : "r"(a))

__device__ __forceinline__ void mma_bf16(float* d, const uint32_t* a,
                                         uint32_t b0, uint32_t b1) {
    asm volatile(
        "mma.sync.aligned.m16n8k16.row.col.f32.bf16.bf16.f32 "
        "{%0,%1,%2,%3}, {%4,%5,%6,%7}, {%8,%9}, {%0,%1,%2,%3};"
        : "+f"(d[0]), "+f"(d[1]), "+f"(d[2]), "+f"(d[3])
        : "r"(a[0]), "r"(a[1]), "r"(a[2]), "r"(a[3]), "r"(b0), "r"(b1));
}

__device__ __forceinline__ uint32_t bfpack(__nv_bfloat16 a, __nv_bfloat16 b) {
    return (uint32_t)__bfloat16_as_ushort(a) | ((uint32_t)__bfloat16_as_ushort(b) << 16);
}

// ---------------- kernel 1: LN stats + gate softmax weights -------------------
__global__ void k_gate(const float* __restrict__ x, const int* __restrict__ dm,
                       const float* __restrict__ gw1, const float* __restrict__ gb1,
                       const float* __restrict__ gw2, const float* __restrict__ gb2) {
    const int t = blockIdx.x * 8 + (threadIdx.x >> 5);
    const int lane = threadIdx.x & 31;
    const float* xr = x + (size_t)t * Hd;

    float s = 0.f, ss = 0.f, a0 = 0.f, a1 = 0.f, a2 = 0.f, a3 = 0.f;
    for (int h = lane * 4; h < Hd; h += 128) {
        float4 xv = *(const float4*)(xr + h);
        s  += xv.x + xv.y + xv.z + xv.w;
        ss += xv.x * xv.x + xv.y * xv.y + xv.z * xv.z + xv.w * xv.w;
        const float4* gw = (const float4*)(gw1 + h * 4);
        float4 w0r = gw[0], w1r = gw[1], w2r = gw[2], w3r = gw[3];
        a0 += xv.x * w0r.x + xv.y * w1r.x + xv.z * w2r.x + xv.w * w3r.x;
        a1 += xv.x * w0r.y + xv.y * w1r.y + xv.z * w2r.y + xv.w * w3r.y;
        a2 += xv.x * w0r.z + xv.y * w1r.z + xv.z * w2r.z + xv.w * w3r.z;
        a3 += xv.x * w0r.w + xv.y * w1r.w + xv.z * w2r.w + xv.w * w3r.w;
    }
    #pragma unroll
    for (int o = 16; o; o >>= 1) {
        s  += __shfl_xor_sync(0xffffffffu, s, o);
        ss += __shfl_xor_sync(0xffffffffu, ss, o);
        a0 += __shfl_xor_sync(0xffffffffu, a0, o);
        a1 += __shfl_xor_sync(0xffffffffu, a1, o);
        a2 += __shfl_xor_sync(0xffffffffu, a2, o);
        a3 += __shfl_xor_sync(0xffffffffu, a3, o);
    }
    if (lane == 0) {
        const float mean = s * (1.f / Hd);
        const float var = ss * (1.f / Hd) - mean * mean;
        g_stats[2 * t] = mean;
        g_stats[2 * t + 1] = rsqrtf(var + 1e-6f);

        float hv[4] = {fmaxf(a0 + gb1[0], 0.f), fmaxf(a1 + gb1[1], 0.f),
                       fmaxf(a2 + gb1[2], 0.f), fmaxf(a3 + gb1[3], 0.f)};
        float lg[4];
        #pragma unroll
        for (int e = 0; e < 4; e++) {
            float acc = gb2[e];
            #pragma unroll
            for (int d = 0; d < 4; d++) acc += hv[d] * gw2[d * 4 + e];
            if (dm[e] == 0) acc = -1e9f;
            lg[e] = acc;
        }
        const float mx = fmaxf(fmaxf(lg[0], lg[1]), fmaxf(lg[2], lg[3]));
        const float e0 = expf(lg[0] - mx), e1 = expf(lg[1] - mx);
        const float e2 = expf(lg[2] - mx), e3 = expf(lg[3] - mx);
        const float inv = 1.f / (e0 + e1 + e2 + e3);
        g_wts[4 * t + 0] = e0 * inv;
        g_wts[4 * t + 1] = e1 * inv;
        g_wts[4 * t + 2] = e2 * inv;
        g_wts[4 * t + 3] = (e1 + e2) * inv;
    }
}

// ---------------- kernel 2a: normalize x + bf16 hi/lo split -------------------
__global__ void k_prepx(const float* __restrict__ x) {
    const int idx = blockIdx.x * 256 + threadIdx.x;   // over Td*Hd/4
    const int t = idx >> 8;
    const int h4 = (idx & 255) * 4;
    const float4 v = *(const float4*)(x + (size_t)t * Hd + h4);
    const float mu = g_stats[2 * t], rs = g_stats[2 * t + 1];
    const float f0 = (v.x - mu) * rs, f1 = (v.y - mu) * rs;
    const float f2 = (v.z - mu) * rs, f3 = (v.w - mu) * rs;
    const __nv_bfloat16 h0 = __float2bfloat16(f0), h1 = __float2bfloat16(f1);
    const __nv_bfloat16 h2 = __float2bfloat16(f2), h3 = __float2bfloat16(f3);
    const __nv_bfloat16 l0 = __float2bfloat16(f0 - __bfloat162float(h0));
    const __nv_bfloat16 l1 = __float2bfloat16(f1 - __bfloat162float(h1));
    const __nv_bfloat16 l2 = __float2bfloat16(f2 - __bfloat162float(h2));
    const __nv_bfloat16 l3 = __float2bfloat16(f3 - __bfloat162float(h3));
    uint2 hw, lw;
    hw.x = bfpack(h0, h1); hw.y = bfpack(h2, h3);
    lw.x = bfpack(l0, l1); lw.y = bfpack(l2, l3);
    *(uint2*)(g_xH + (size_t)t * Hd + h4) = hw;
    *(uint2*)(g_xL + (size_t)t * Hd + h4) = lw;
}

// ---------------- kernel 2b: transpose + scale + bf16-split W1 ----------------
__global__ void k_trans1(const float* __restrict__ w1, const float* __restrict__ sb,
                         const float* __restrict__ si) {
    __shared__ float t[32][33];
    const int tx = threadIdx.x, ty = threadIdx.y;
    const int f0 = blockIdx.x * 32, h0 = blockIdx.y * 32;
    #pragma unroll
    for (int i = 0; i < 4; i++) {
        const int h = h0 + ty + i * 8;
        t[ty + i * 8][tx] = w1[(size_t)h * Fd + f0 + tx];
    }
    __syncthreads();
    const int h = h0 + tx;
    const float s_b = sb[h], s_i = si[h];
    #pragma unroll
    for (int i = 0; i < 4; i++) {
        const int fo = f0 + ty + i * 8;
        const float w = t[tx][ty + i * 8];
        const size_t o = (size_t)fo * Hd + h;
        const float vb = w * s_b;
        const __nv_bfloat16 hb = __float2bfloat16(vb);
        g_BbH[o] = hb;
        g_BbL[o] = __float2bfloat16(vb - __bfloat162float(hb));
        const float vi = w * s_i;
        const __nv_bfloat16 hi = __float2bfloat16(vi);
        g_BiH[o] = hi;
        g_BiL[o] = __float2bfloat16(vi - __bfloat162float(hi));
    }
}

// ---------------- kernel 2c: transpose + bf16-split W2 ------------------------
__global__ void k_trans2(const float* __restrict__ w2) {
    __shared__ float t[32][33];
    const int tx = threadIdx.x, ty = threadIdx.y;
    const int h0 = blockIdx.x * 32, f0 = blockIdx.y * 32;
    #pragma unroll
    for (int i = 0; i < 4; i++) {
        const int f = f0 + ty + i * 8;
        t[ty + i * 8][tx] = w2[(size_t)f * Hd + h0 + tx];
    }
    __syncthreads();
    const int f = f0 + tx;
    #pragma unroll
    for (int i = 0; i < 4; i++) {
        const int ho = h0 + ty + i * 8;
        const float w = t[tx][ty + i * 8];
        const size_t o = (size_t)ho * Fd + f;
        const __nv_bfloat16 hb = __float2bfloat16(w);
        g_W2H[o] = hb;
        g_W2L[o] = __float2bfloat16(w - __bfloat162float(hb));
    }
}

// ---------------- kernel 2d: c_d = b_d @ W1 + ad_b1 ---------------------------
__global__ void k_prepc(const float* __restrict__ w1, const float* __restrict__ bb,
                        const float* __restrict__ bi, const float* __restrict__ ab1) {
    const int i = blockIdx.x * 256 + threadIdx.x;  // 0..2*Fd-1
    const int d = i >> 11;
    const int f = i & (Fd - 1);
    const float* bv = d ? bi : bb;
    float a0 = 0.f, a1 = 0.f, a2 = 0.f, a3 = 0.f;
    #pragma unroll 8
    for (int h = 0; h < Hd; h += 4) {
        a0 = fmaf(__ldg(bv + h + 0), w1[(size_t)(h + 0) * Fd + f], a0);
        a1 = fmaf(__ldg(bv + h + 1), w1[(size_t)(h + 1) * Fd + f], a1);
        a2 = fmaf(__ldg(bv + h + 2), w1[(size_t)(h + 2) * Fd + f], a2);
        a3 = fmaf(__ldg(bv + h + 3), w1[(size_t)(h + 3) * Fd + f], a3);
    }
    g_cvec[d][f] = ab1[f] + ((a0 + a1) + (a2 + a3));
}

// ---------------- kernel 3: up GEMM (mma.sync bf16 3-term), fused epilogue ----
// CTA 128m x 64f, 8 warps: dom = wid>>2 (0=book,1=iwslt), 2m x 2n within dom,
// warp tile 64m x 32f. Smem per buf (32KB): AH 8K | AL 8K | B(dom,term) 4x4K.
// Epilogue: dom1 writes w2*relu to smem, dom0 combines, writes bf16 hi/lo g.
#define UP_SMEM 65536
__global__ void __launch_bounds__(256, 1) k_up_mma() {
    extern __shared__ char smem[];
    const uint32_t sm = smem_u32(smem);
    const int tid = threadIdx.x, lane = tid & 31, wid = tid >> 5;
    const int m0 = blockIdx.y * 128, n0 = blockIdx.x * 64;
    const int dom = wid >> 2, wm = wid & 1, wn = (wid >> 1) & 1;
    const int mw = wm * 64, nw = wn * 32;
    const int aRow = lane & 15, aK = lane >> 4;
    const int bRow = (lane & 7) + ((lane >> 4) << 3), bK = (lane >> 3) & 1;

    float acc[4][4][4];
    #pragma unroll
    for (int i = 0; i < 4; i++)
        #pragma unroll
        for (int n = 0; n < 4; n++)
            #pragma unroll
            for (int q = 0; q < 4; q++) acc[i][n][q] = 0.f;

    auto load_tiles = [&](int c, int buf) {
        const uint32_t db = sm + buf * 32768;
        #pragma unroll
        for (int rep = 0; rep < 2; rep++) {
            const int idx = tid + rep * 256;
            const int r = idx & 127, kb = idx >> 7;
            const size_t go = (size_t)(m0 + r) * Hd + c * 32 + kb * 8;
            CP16(db + idx * 16, g_xH + go);
            CP16(db + 8192 + idx * 16, g_xL + go);
        }
        {
            const int f = tid & 63, kb = tid >> 6;
            const size_t go = (size_t)(n0 + f) * Hd + c * 32 + kb * 8;
            const uint32_t so = db + 16384 + tid * 16;
            CP16(so + 0,     g_BbH + go);
            CP16(so + 4096,  g_BbL + go);
            CP16(so + 8192,  g_BiH + go);
            CP16(so + 12288, g_BiL + go);
        }
        CP_COMMIT();
    };

    load_tiles(0, 0);
    CP_WAIT0();
    __syncthreads();

    #pragma unroll 1
    for (int c = 0; c < 32; c++) {
        const int buf = c & 1;
        if (c < 31) load_tiles(c + 1, buf ^ 1);
        const uint32_t smA = sm + buf * 32768;
        const uint32_t smB = smA + 16384 + dom * 8192;
        #pragma unroll
        for (int j = 0; j < 2; j++) {
            uint32_t aH[4][4], aL[4][4];
            const uint32_t aBase = smA + (((2 * j + aK) << 7) + mw + aRow) * 16;
            #pragma unroll
            for (int i = 0; i < 4; i++) {
                LDSM4(aH[i], aBase + i * 256);
                LDSM4(aL[i], aBase + 8192 + i * 256);
            }
            uint32_t bH[2][4], bL[2][4];
            const uint32_t bBase = smB + (((2 * j + bK) << 6) + nw + bRow) * 16;
            LDSM4(bH[0], bBase);
            LDSM4(bH[1], bBase + 256);
            LDSM4(bL[0], bBase + 4096);
            LDSM4(bL[1], bBase + 4096 + 256);
            #pragma unroll
            for (int i = 0; i < 4; i++)
                #pragma unroll
                for (int p = 0; p < 2; p++)
                    #pragma unroll
                    for (int h = 0; h < 2; h++) {
                        const int nf = 2 * p + h;
                        mma_bf16(acc[i][nf], aH[i], bH[p][2*h], bH[p][2*h+1]);
                        mma_bf16(acc[i][nf], aH[i], bL[p][2*h], bL[p][2*h+1]);
                        mma_bf16(acc[i][nf], aL[i], bH[p][2*h], bH[p][2*h+1]);
                    }
        }
        if (c < 31) { CP_WAIT0(); __syncthreads(); }
    }

    // --- epilogue ------------------------------------------------------------
    __syncthreads();   // all LDSM reads done before smem reuse
    const int g = lane >> 2, tq = lane & 3;
    if (dom == 1) {
        #pragma unroll
        for (int i = 0; i < 4; i++) {
            const int r0 = mw + 16 * i + g;
            const float w2a = g_wts[4 * (m0 + r0) + 2];
            const float w2b = g_wts[4 * (m0 + r0 + 8) + 2];
            #pragma unroll
            for (int nf = 0; nf < 4; nf++) {
                const int fl = nw + nf * 8 + 2 * tq;
                const int fg = n0 + fl;
                const float cv0 = g_cvec[1][fg], cv1 = g_cvec[1][fg + 1];
                float2 v0, v1;
                v0.x = w2a * fmaxf(acc[i][nf][0] + cv0, 0.f);
                v0.y = w2a * fmaxf(acc[i][nf][1] + cv1, 0.f);
                v1.x = w2b * fmaxf(acc[i][nf][2] + cv0, 0.f);
                v1.y = w2b * fmaxf(acc[i][nf][3] + cv1, 0.f);
                *(float2*)(smem + ((size_t)r0 * 72 + fl) * 4) = v0;
                *(float2*)(smem + ((size_t)(r0 + 8) * 72 + fl) * 4) = v1;
            }
        }
    }
    __syncthreads();
    if (dom == 0) {
        #pragma unroll
        for (int i = 0; i < 4; i++) {
            const int r0 = mw + 16 * i + g;
            const float w1a = g_wts[4 * (m0 + r0) + 1];
            const float w1b = g_wts[4 * (m0 + r0 + 8) + 1];
            #pragma unroll
            for (int nf = 0; nf < 4; nf++) {
                const int fl = nw + nf * 8 + 2 * tq;
                const int fg = n0 + fl;
                const float cv0 = g_cvec[0][fg], cv1 = g_cvec[0][fg + 1];
                const float2 s0 = *(const float2*)(smem + ((size_t)r0 * 72 + fl) * 4);
                const float2 s1 = *(const float2*)(smem + ((size_t)(r0 + 8) * 72 + fl) * 4);
                const float g0 = w1a * fmaxf(acc[i][nf][0] + cv0, 0.f) + s0.x;
                const float g1 = w1a * fmaxf(acc[i][nf][1] + cv1, 0.f) + s0.y;
                const float g2 = w1b * fmaxf(acc[i][nf][2] + cv0, 0.f) + s1.x;
                const float g3 = w1b * fmaxf(acc[i][nf][3] + cv1, 0.f) + s1.y;
                const __nv_bfloat16 h0 = __float2bfloat16(g0), h1 = __float2bfloat16(g1);
                const __nv_bfloat16 h2 = __float2bfloat16(g2), h3 = __float2bfloat16(g3);
                const size_t o0 = (size_t)(m0 + r0) * Fd + fg;
                const size_t o1 = (size_t)(m0 + r0 + 8) * Fd + fg;
                *(uint32_t*)(g_ghi + o0) = bfpack(h0, h1);
                *(uint32_t*)(g_ghi + o1) = bfpack(h2, h3);
                *(uint32_t*)(g_glo + o0) =
                    bfpack(__float2bfloat16(g0 - __bfloat162float(h0)),
                           __float2bfloat16(g1 - __bfloat162float(h1)));
                *(uint32_t*)(g_glo + o1) =
                    bfpack(__float2bfloat16(g2 - __bfloat162float(h2)),
                           __float2bfloat16(g3 - __bfloat162float(h3)));
            }
        }
    }
}

// ---------------- kernel 4: down GEMM (mma.sync bf16 3-term) + residual -------
// CTA 128m x 128h, 8 warps 2m x 4n, warp 64x32.
// Smem per buf (32KB): AH 8K | AL 8K | BH 8K | BL 8K.
#define DN_SMEM 65536
__global__ void __launch_bounds__(256, 1) k_down_mma(const float* __restrict__ x,
                                                     const float* __restrict__ b2,
                                                     float* __restrict__ out) {
    extern __shared__ char smem[];
    const uint32_t sm = smem_u32(smem);
    const int tid = threadIdx.x, lane = tid & 31, wid = tid >> 5;
    const int m0 = blockIdx.y * 128, n0 = blockIdx.x * 128;
    const int wm = wid & 1, wn = wid >> 1;
    const int mw = wm * 64, nw = wn * 32;
    const int aRow = lane & 15, aK = lane >> 4;
    const int bRow = (lane & 7) + ((lane >> 4) << 3), bK = (lane >> 3) & 1;

    float acc[4][4][4];
    #pragma unroll
    for (int i = 0; i < 4; i++)
        #pragma unroll
        for (int n = 0; n < 4; n++)
            #pragma unroll
            for (int q = 0; q < 4; q++) acc[i][n][q] = 0.f;

    auto load_tiles = [&](int c, int buf) {
        const uint32_t db = sm + buf * 32768;
        #pragma unroll
        for (int rep = 0; rep < 2; rep++) {
            const int idx = tid + rep * 256;
            const int r = idx & 127, kb = idx >> 7;
            const size_t ga = (size_t)(m0 + r) * Fd + c * 32 + kb * 8;
            const size_t gb = (size_t)(n0 + r) * Fd + c * 32 + kb * 8;
            CP16(db + idx * 16, g_ghi + ga);
            CP16(db + 8192 + idx * 16, g_glo + ga);
            CP16(db + 16384 + idx * 16, g_W2H + gb);
            CP16(db + 24576 + idx * 16, g_W2L + gb);
        }
        CP_COMMIT();
    };

    load_tiles(0, 0);
    CP_WAIT0();
    __syncthreads();

    #pragma unroll 1
    for (int c = 0; c < 64; c++) {
        const int buf = c & 1;
        if (c < 63) load_tiles(c + 1, buf ^ 1);
        const uint32_t smA = sm + buf * 32768;
        const uint32_t smB = smA + 16384;
        #pragma unroll
        for (int j = 0; j < 2; j++) {
            uint32_t aH[4][4], aL[4][4];
            const uint32_t aBase = smA + (((2 * j + aK) << 7) + mw + aRow) * 16;
            #pragma unroll
            for (int i = 0; i < 4; i++) {
                LDSM4(aH[i], aBase + i * 256);
                LDSM4(aL[i], aBase + 8192 + i * 256);
            }
            uint32_t bH[2][4], bL[2][4];
            const uint32_t bBase = smB + (((2 * j + bK) << 7) + nw + bRow) * 16;
            LDSM4(bH[0], bBase);
            LDSM4(bH[1], bBase + 256);
            LDSM4(bL[0], bBase + 8192);
            LDSM4(bL[1], bBase + 8192 + 256);
            #pragma unroll
            for (int i = 0; i < 4; i++)
                #pragma unroll
                for (int p = 0; p < 2; p++)
                    #pragma unroll
                    for (int h = 0; h < 2; h++) {
                        const int nf = 2 * p + h;
                        mma_bf16(acc[i][nf], aH[i], bH[p][2*h], bH[p][2*h+1]);
                        mma_bf16(acc[i][nf], aH[i], bL[p][2*h], bL[p][2*h+1]);
                        mma_bf16(acc[i][nf], aL[i], bH[p][2*h], bH[p][2*h+1]);
                    }
        }
        if (c < 63) { CP_WAIT0(); __syncthreads(); }
    }

    // --- epilogue: out = x*(1+w0) + acc + (w1+w2)*b2 --------------------------
    const int g = lane >> 2, tq = lane & 3;
    #pragma unroll
    for (int i = 0; i < 4; i++) {
        const int r0 = m0 + mw + 16 * i + g;
        const float4 wv0 = *(const float4*)&g_wts[4 * r0];
        const float4 wv1 = *(const float4*)&g_wts[4 * (r0 + 8)];
        const float xs0 = 1.f + wv0.x, w120 = wv0.w;
        const float xs1 = 1.f + wv1.x, w121 = wv1.w;
        #pragma unroll
        for (int nf = 0; nf < 4; nf++) {
            const int h = n0 + nw + nf * 8 + 2 * tq;
            const float2 xa = *(const float2*)&x[(size_t)r0 * Hd + h];
            const float2 xb = *(const float2*)&x[(size_t)(r0 + 8) * Hd + h];
            const float2 bv = *(const float2*)&b2[h];
            float2 o0, o1;
            o0.x = xa.x * xs0 + acc[i][nf][0] + w120 * bv.x;
            o0.y = xa.y * xs0 + acc[i][nf][1] + w120 * bv.y;
            o1.x = xb.x * xs1 + acc[i][nf][2] + w121 * bv.x;
            o1.y = xb.y * xs1 + acc[i][nf][3] + w121 * bv.y;
            *(float2*)&out[(size_t)r0 * Hd + h] = o0;
            *(float2*)&out[(size_t)(r0 + 8) * Hd + h] = o1;
        }
    }
}

// ---------------- launch ------------------------------------------------------
extern "C" void kernel_launch(void* const* d_in, const int* in_sizes, int n_in,
                              void* d_out, int out_size) {
    const float* x   = (const float*)d_in[0];
    const int*   dm  = (const int*)d_in[1];
    const float* gw1 = (const float*)d_in[2];
    const float* gb1 = (const float*)d_in[3];
    const float* gw2 = (const float*)d_in[4];
    const float* gb2 = (const float*)d_in[5];
    const float* sb  = (const float*)d_in[6];
    const float* bb  = (const float*)d_in[7];
    const float* si  = (const float*)d_in[8];
    const float* bi  = (const float*)d_in[9];
    const float* aw1 = (const float*)d_in[10];
    const float* ab1 = (const float*)d_in[11];
    const float* aw2 = (const float*)d_in[12];
    const float* ab2 = (const float*)d_in[13];
    float* out = (float*)d_out;

    cudaFuncSetAttribute(k_up_mma, cudaFuncAttributeMaxDynamicSharedMemorySize, UP_SMEM);
    cudaFuncSetAttribute(k_down_mma, cudaFuncAttributeMaxDynamicSharedMemorySize, DN_SMEM);

    k_gate<<<Td / 8, 256>>>(x, dm, gw1, gb1, gw2, gb2);
    k_prepx<<<(Td * (Hd / 4)) / 256, 256>>>(x);
    k_trans1<<<dim3(Fd / 32, Hd / 32), dim3(32, 8)>>>(aw1, sb, si);
    k_trans2<<<dim3(Hd / 32, Fd / 32), dim3(32, 8)>>>(aw2);
    k_prepc<<<(2 * Fd) / 256, 256>>>(aw1, bb, bi, ab1);
    k_up_mma<<<dim3(Fd / 64, Td / 128), 256, UP_SMEM>>>();
    k_down_mma<<<dim3(Hd / 128, Td / 128), 256, DN_SMEM>>>(x, ab2, out);
}

// round 5
// speedup vs baseline: 3.1367x; 2.4442x over previous
#include <cuda_runtime.h>
#include <cuda_fp16.h>
#include <cstdint>

#define Hd 1024
#define Fd 2048
#define Td 8192

// ---------------- scratch (__device__ globals; no allocs allowed) -------------
__device__ __align__(16) float g_stats[Td * 2];  // mean, rstd per token (unused after fuse, kept)
__device__ __align__(16) float g_wts[Td * 4];    // w0, w1, w2, w1+w2
__device__ __align__(16) float g_cvec[2][Fd];    // b_d @ ad_w1 + ad_b1
__device__ __align__(16) __half g_xh[(size_t)Td * Hd];   // norm(x) fp16
__device__ __align__(16) __half g_Bb[(size_t)Fd * Hd];   // (W1*s_book)^T fp16
__device__ __align__(16) __half g_Bi[(size_t)Fd * Hd];   // (W1*s_iwslt)^T fp16
__device__ __align__(16) __half g_W2[(size_t)Hd * Fd];   // W2^T fp16
__device__ __align__(16) __half g_g[(size_t)Td * Fd];    // combined activation fp16

// ---------------- PTX helpers -------------------------------------------------
__device__ __forceinline__ uint32_t smem_u32(const void* p) {
    uint32_t a;
    asm("{ .reg .u64 t; cvta.to.shared.u64 t, %1; cvt.u32.u64 %0, t; }"
        : "=r"(a) : "l"(p));
    return a;
}
#define CP16(dst, src) \
    asm volatile("cp.async.cg.shared.global [%0], [%1], 16;" \
                 :: "r"(dst), "l"(__cvta_generic_to_global(src)))
#define CP_COMMIT() asm volatile("cp.async.commit_group;" ::: "memory")
#define CP_WAITG(n) asm volatile("cp.async.wait_group %0;" :: "n"(n) : "memory")
#define LDSM4(r, a) \
    asm volatile("ldmatrix.sync.aligned.m8n8.x4.shared.b16 {%0,%1,%2,%3}, [%4];" \
                 : "=r"((r)[0]), "=r"((r)[1]), "=r"((r)[2]), "=r"((r)[3]) : "r"(a))

__device__ __forceinline__ void mma_f16(float* d, const uint32_t* a,
                                        uint32_t b0, uint32_t b1) {
    asm volatile(
        "mma.sync.aligned.m16n8k16.row.col.f32.f16.f16.f32 "
        "{%0,%1,%2,%3}, {%4,%5,%6,%7}, {%8,%9}, {%0,%1,%2,%3};"
        : "+f"(d[0]), "+f"(d[1]), "+f"(d[2]), "+f"(d[3])
        : "r"(a[0]), "r"(a[1]), "r"(a[2]), "r"(a[3]), "r"(b0), "r"(b1));
}

__device__ __forceinline__ uint32_t hpack(float a, float b) {
    const __half2 h = __floats2half2_rn(a, b);
    return *(const uint32_t*)&h;
}

// ---------------- kernel 1: LN stats + gate weights + norm(x)->fp16 -----------
__global__ void k_gate(const float* __restrict__ x, const int* __restrict__ dm,
                       const float* __restrict__ gw1, const float* __restrict__ gb1,
                       const float* __restrict__ gw2, const float* __restrict__ gb2) {
    const int t = blockIdx.x * 8 + (threadIdx.x >> 5);
    const int lane = threadIdx.x & 31;
    const float* xr = x + (size_t)t * Hd;

    float4 xv[8];
    float s = 0.f, ss = 0.f, a0 = 0.f, a1 = 0.f, a2 = 0.f, a3 = 0.f;
    #pragma unroll
    for (int it = 0; it < 8; it++) {
        const int h = lane * 4 + it * 128;
        xv[it] = *(const float4*)(xr + h);
        const float4 v = xv[it];
        s  += v.x + v.y + v.z + v.w;
        ss += v.x * v.x + v.y * v.y + v.z * v.z + v.w * v.w;
        const float4* gw = (const float4*)(gw1 + h * 4);
        float4 w0r = gw[0], w1r = gw[1], w2r = gw[2], w3r = gw[3];
        a0 += v.x * w0r.x + v.y * w1r.x + v.z * w2r.x + v.w * w3r.x;
        a1 += v.x * w0r.y + v.y * w1r.y + v.z * w2r.y + v.w * w3r.y;
        a2 += v.x * w0r.z + v.y * w1r.z + v.z * w2r.z + v.w * w3r.z;
        a3 += v.x * w0r.w + v.y * w1r.w + v.z * w2r.w + v.w * w3r.w;
    }
    #pragma unroll
    for (int o = 16; o; o >>= 1) {
        s  += __shfl_xor_sync(0xffffffffu, s, o);
        ss += __shfl_xor_sync(0xffffffffu, ss, o);
        a0 += __shfl_xor_sync(0xffffffffu, a0, o);
        a1 += __shfl_xor_sync(0xffffffffu, a1, o);
        a2 += __shfl_xor_sync(0xffffffffu, a2, o);
        a3 += __shfl_xor_sync(0xffffffffu, a3, o);
    }
    const float mean = s * (1.f / Hd);
    const float var = ss * (1.f / Hd) - mean * mean;
    const float rstd = rsqrtf(var + 1e-6f);

    // normalize + fp16 store
    #pragma unroll
    for (int it = 0; it < 8; it++) {
        const int h = lane * 4 + it * 128;
        const float4 v = xv[it];
        uint2 o;
        o.x = hpack((v.x - mean) * rstd, (v.y - mean) * rstd);
        o.y = hpack((v.z - mean) * rstd, (v.w - mean) * rstd);
        *(uint2*)(g_xh + (size_t)t * Hd + h) = o;
    }

    if (lane == 0) {
        g_stats[2 * t] = mean;
        g_stats[2 * t + 1] = rstd;
        float hv[4] = {fmaxf(a0 + gb1[0], 0.f), fmaxf(a1 + gb1[1], 0.f),
                       fmaxf(a2 + gb1[2], 0.f), fmaxf(a3 + gb1[3], 0.f)};
        float lg[4];
        #pragma unroll
        for (int e = 0; e < 4; e++) {
            float acc = gb2[e];
            #pragma unroll
            for (int d = 0; d < 4; d++) acc += hv[d] * gw2[d * 4 + e];
            if (dm[e] == 0) acc = -1e9f;
            lg[e] = acc;
        }
        const float mx = fmaxf(fmaxf(lg[0], lg[1]), fmaxf(lg[2], lg[3]));
        const float e0 = expf(lg[0] - mx), e1 = expf(lg[1] - mx);
        const float e2 = expf(lg[2] - mx), e3 = expf(lg[3] - mx);
        const float inv = 1.f / (e0 + e1 + e2 + e3);
        g_wts[4 * t + 0] = e0 * inv;
        g_wts[4 * t + 1] = e1 * inv;
        g_wts[4 * t + 2] = e2 * inv;
        g_wts[4 * t + 3] = (e1 + e2) * inv;
    }
}

// ---------------- kernel 2a: transpose + scale W1 -> fp16, both domains -------
__global__ void k_trans1(const float* __restrict__ w1, const float* __restrict__ sb,
                         const float* __restrict__ si) {
    __shared__ float t[32][33];
    const int tx = threadIdx.x, ty = threadIdx.y;
    const int f0 = blockIdx.x * 32, h0 = blockIdx.y * 32;
    #pragma unroll
    for (int i = 0; i < 4; i++) {
        const int h = h0 + ty + i * 8;
        t[ty + i * 8][tx] = w1[(size_t)h * Fd + f0 + tx];
    }
    __syncthreads();
    const int h = h0 + tx;
    const float s_b = sb[h], s_i = si[h];
    #pragma unroll
    for (int i = 0; i < 4; i++) {
        const int fo = f0 + ty + i * 8;
        const float w = t[tx][ty + i * 8];
        const size_t o = (size_t)fo * Hd + h;
        g_Bb[o] = __float2half_rn(w * s_b);
        g_Bi[o] = __float2half_rn(w * s_i);
    }
}

// ---------------- kernel 2b: transpose W2 -> fp16 -----------------------------
__global__ void k_trans2(const float* __restrict__ w2) {
    __shared__ float t[32][33];
    const int tx = threadIdx.x, ty = threadIdx.y;
    const int h0 = blockIdx.x * 32, f0 = blockIdx.y * 32;
    #pragma unroll
    for (int i = 0; i < 4; i++) {
        const int f = f0 + ty + i * 8;
        t[ty + i * 8][tx] = w2[(size_t)f * Hd + h0 + tx];
    }
    __syncthreads();
    const int f = f0 + tx;
    #pragma unroll
    for (int i = 0; i < 4; i++) {
        const int ho = h0 + ty + i * 8;
        g_W2[(size_t)ho * Fd + f] = __float2half_rn(t[tx][ty + i * 8]);
    }
}

// ---------------- kernel 2c: c_d = b_d @ W1 + ad_b1 (fp32 exact) --------------
__global__ void k_prepc(const float* __restrict__ w1, const float* __restrict__ bb,
                        const float* __restrict__ bi, const float* __restrict__ ab1) {
    const int i = blockIdx.x * 256 + threadIdx.x;  // 0..2*Fd-1
    const int d = i >> 11;
    const int f = i & (Fd - 1);
    const float* bv = d ? bi : bb;
    float a0 = 0.f, a1 = 0.f, a2 = 0.f, a3 = 0.f;
    #pragma unroll 8
    for (int h = 0; h < Hd; h += 4) {
        a0 = fmaf(__ldg(bv + h + 0), w1[(size_t)(h + 0) * Fd + f], a0);
        a1 = fmaf(__ldg(bv + h + 1), w1[(size_t)(h + 1) * Fd + f], a1);
        a2 = fmaf(__ldg(bv + h + 2), w1[(size_t)(h + 2) * Fd + f], a2);
        a3 = fmaf(__ldg(bv + h + 3), w1[(size_t)(h + 3) * Fd + f], a3);
    }
    g_cvec[d][f] = ab1[f] + ((a0 + a1) + (a2 + a3));
}

// ---------------- kernel 3: up GEMM, both domains, fused gate-combine ---------
// CTA 128m x 128f(per domain). 8 warps: dom=wid>>2, within 2m x 2n, warp 64x64.
// Stage (24KB): A 128x32 fp16 (8K) | B_book 128x32 (8K) | B_iwslt 128x32 (8K).
// 4 stages = 96KB. Epilogue exchange 128x132 f32 = 67.6KB reuses the smem.
#define UP_SMEM  98304
#define UP_STAGE 24576
__global__ void __launch_bounds__(256, 1) k_up() {
    extern __shared__ char smem[];
    const uint32_t sm = smem_u32(smem);
    const int tid = threadIdx.x, lane = tid & 31, wid = tid >> 5;
    const int m0 = blockIdx.y * 128, n0 = blockIdx.x * 128;
    const int dom = wid >> 2, wsub = wid & 3;
    const int mw = (wsub >> 1) * 64, nw = (wsub & 1) * 64;
    const int aRow = lane & 15, aK = lane >> 4;
    const int bRow = (lane & 7) + ((lane >> 4) << 3), bK = (lane >> 3) & 1;
    const __half* Bsrc[2] = {g_Bb, g_Bi};

    float acc[4][8][4];
    #pragma unroll
    for (int i = 0; i < 4; i++)
        #pragma unroll
        for (int n = 0; n < 8; n++)
            #pragma unroll
            for (int q = 0; q < 4; q++) acc[i][n][q] = 0.f;

    auto load = [&](int c) {
        const uint32_t sb = sm + (c & 3) * UP_STAGE;
        #pragma unroll
        for (int rep = 0; rep < 2; rep++) {
            const int idx = tid + rep * 256;
            const int r = idx & 127, kb = idx >> 7;
            CP16(sb + idx * 16, g_xh + (size_t)(m0 + r) * Hd + c * 32 + kb * 8);
        }
        #pragma unroll
        for (int rep = 0; rep < 4; rep++) {
            const int u = tid + rep * 256;
            const int d = u >> 9, within = u & 511;
            const int f = within & 127, kb = within >> 7;
            CP16(sb + 8192 + d * 8192 + within * 16,
                 Bsrc[d] + (size_t)(n0 + f) * Hd + c * 32 + kb * 8);
        }
        CP_COMMIT();
    };

    load(0); load(1); load(2);

    #pragma unroll 1
    for (int c = 0; c < 32; c++) {
        if (c < 29) CP_WAITG(2); else CP_WAITG(0);
        __syncthreads();
        if (c + 3 < 32) load(c + 3);
        const uint32_t smA = sm + (c & 3) * UP_STAGE;
        const uint32_t smB = smA + 8192 + dom * 8192;
        #pragma unroll
        for (int j = 0; j < 2; j++) {
            uint32_t a[4][4];
            const uint32_t aBase = smA + (((2 * j + aK) << 7) + mw + aRow) * 16;
            #pragma unroll
            for (int i = 0; i < 4; i++) LDSM4(a[i], aBase + i * 256);
            uint32_t b[4][4];
            const uint32_t bBase = smB + (((2 * j + bK) << 7) + nw + bRow) * 16;
            #pragma unroll
            for (int nb = 0; nb < 4; nb++) LDSM4(b[nb], bBase + nb * 256);
            #pragma unroll
            for (int i = 0; i < 4; i++)
                #pragma unroll
                for (int nb = 0; nb < 4; nb++) {
                    mma_f16(acc[i][2 * nb + 0], a[i], b[nb][0], b[nb][1]);
                    mma_f16(acc[i][2 * nb + 1], a[i], b[nb][2], b[nb][3]);
                }
        }
    }

    // --- epilogue: dom1 -> smem (w2*relu), dom0 combines, writes g fp16 -------
    __syncthreads();
    const int g = lane >> 2, tq = lane & 3;
    float* ex = (float*)smem;               // [128][132]
    if (dom == 1) {
        #pragma unroll
        for (int i = 0; i < 4; i++) {
            const int r = mw + 16 * i + g;
            const float w2a = g_wts[4 * (m0 + r) + 2];
            const float w2b = g_wts[4 * (m0 + r + 8) + 2];
            #pragma unroll
            for (int n = 0; n < 8; n++) {
                const int col = nw + 8 * n + 2 * tq;
                const float cv0 = g_cvec[1][n0 + col], cv1 = g_cvec[1][n0 + col + 1];
                float2 v0, v1;
                v0.x = w2a * fmaxf(acc[i][n][0] + cv0, 0.f);
                v0.y = w2a * fmaxf(acc[i][n][1] + cv1, 0.f);
                v1.x = w2b * fmaxf(acc[i][n][2] + cv0, 0.f);
                v1.y = w2b * fmaxf(acc[i][n][3] + cv1, 0.f);
                *(float2*)(ex + (size_t)r * 132 + col) = v0;
                *(float2*)(ex + (size_t)(r + 8) * 132 + col) = v1;
            }
        }
    }
    __syncthreads();
    if (dom == 0) {
        #pragma unroll
        for (int i = 0; i < 4; i++) {
            const int r = mw + 16 * i + g;
            const float w1a = g_wts[4 * (m0 + r) + 1];
            const float w1b = g_wts[4 * (m0 + r + 8) + 1];
            #pragma unroll
            for (int n = 0; n < 8; n++) {
                const int col = nw + 8 * n + 2 * tq;
                const float cv0 = g_cvec[0][n0 + col], cv1 = g_cvec[0][n0 + col + 1];
                const float2 s0 = *(const float2*)(ex + (size_t)r * 132 + col);
                const float2 s1 = *(const float2*)(ex + (size_t)(r + 8) * 132 + col);
                const float g0 = w1a * fmaxf(acc[i][n][0] + cv0, 0.f) + s0.x;
                const float g1 = w1a * fmaxf(acc[i][n][1] + cv1, 0.f) + s0.y;
                const float g2 = w1b * fmaxf(acc[i][n][2] + cv0, 0.f) + s1.x;
                const float g3 = w1b * fmaxf(acc[i][n][3] + cv1, 0.f) + s1.y;
                *(uint32_t*)(g_g + (size_t)(m0 + r) * Fd + n0 + col) = hpack(g0, g1);
                *(uint32_t*)(g_g + (size_t)(m0 + r + 8) * Fd + n0 + col) = hpack(g2, g3);
            }
        }
    }
}

// ---------------- kernel 4: down GEMM + residual + gated mix ------------------
// CTA 128m x 256h. 8 warps 2m x 4n, warp 64x64.
// Stage (24KB): A 128x32 fp16 (8K) | B 256x32 fp16 (16K). 4 stages = 96KB.
#define DN_SMEM  98304
#define DN_STAGE 24576
__global__ void __launch_bounds__(256, 1) k_down(const float* __restrict__ x,
                                                 const float* __restrict__ b2,
                                                 float* __restrict__ out) {
    extern __shared__ char smem[];
    const uint32_t sm = smem_u32(smem);
    const int tid = threadIdx.x, lane = tid & 31, wid = tid >> 5;
    const int m0 = blockIdx.y * 128, n0 = blockIdx.x * 256;
    const int mw = (wid & 1) * 64, nw = (wid >> 1) * 64;
    const int aRow = lane & 15, aK = lane >> 4;
    const int bRow = (lane & 7) + ((lane >> 4) << 3), bK = (lane >> 3) & 1;

    float acc[4][8][4];
    #pragma unroll
    for (int i = 0; i < 4; i++)
        #pragma unroll
        for (int n = 0; n < 8; n++)
            #pragma unroll
            for (int q = 0; q < 4; q++) acc[i][n][q] = 0.f;

    auto load = [&](int c) {
        const uint32_t sb = sm + (c & 3) * DN_STAGE;
        #pragma unroll
        for (int rep = 0; rep < 2; rep++) {
            const int idx = tid + rep * 256;
            const int r = idx & 127, kb = idx >> 7;
            CP16(sb + idx * 16, g_g + (size_t)(m0 + r) * Fd + c * 32 + kb * 8);
        }
        #pragma unroll
        for (int rep = 0; rep < 4; rep++) {
            const int u = tid + rep * 256;          // kb*256 + h
            const int h = u & 255, kb = u >> 8;
            CP16(sb + 8192 + u * 16, g_W2 + (size_t)(n0 + h) * Fd + c * 32 + kb * 8);
        }
        CP_COMMIT();
    };

    load(0); load(1); load(2);

    #pragma unroll 1
    for (int c = 0; c < 64; c++) {
        if (c < 61) CP_WAITG(2); else CP_WAITG(0);
        __syncthreads();
        if (c + 3 < 64) load(c + 3);
        const uint32_t smA = sm + (c & 3) * DN_STAGE;
        const uint32_t smB = smA + 8192;
        #pragma unroll
        for (int j = 0; j < 2; j++) {
            uint32_t a[4][4];
            const uint32_t aBase = smA + (((2 * j + aK) << 7) + mw + aRow) * 16;
            #pragma unroll
            for (int i = 0; i < 4; i++) LDSM4(a[i], aBase + i * 256);
            uint32_t b[4][4];
            const uint32_t bBase = smB + (((2 * j + bK) << 8) + nw + bRow) * 16;
            #pragma unroll
            for (int nb = 0; nb < 4; nb++) LDSM4(b[nb], bBase + nb * 256);
            #pragma unroll
            for (int i = 0; i < 4; i++)
                #pragma unroll
                for (int nb = 0; nb < 4; nb++) {
                    mma_f16(acc[i][2 * nb + 0], a[i], b[nb][0], b[nb][1]);
                    mma_f16(acc[i][2 * nb + 1], a[i], b[nb][2], b[nb][3]);
                }
        }
    }

    // --- epilogue: out = x*(1+w0) + acc + (w1+w2)*b2 --------------------------
    const int g = lane >> 2, tq = lane & 3;
    #pragma unroll
    for (int i = 0; i < 4; i++) {
        const int r0 = m0 + mw + 16 * i + g;
        const float4 wv0 = *(const float4*)&g_wts[4 * r0];
        const float4 wv1 = *(const float4*)&g_wts[4 * (r0 + 8)];
        const float xs0 = 1.f + wv0.x, w120 = wv0.w;
        const float xs1 = 1.f + wv1.x, w121 = wv1.w;
        #pragma unroll
        for (int n = 0; n < 8; n++) {
            const int h = n0 + nw + 8 * n + 2 * tq;
            const float2 xa = *(const float2*)&x[(size_t)r0 * Hd + h];
            const float2 xb = *(const float2*)&x[(size_t)(r0 + 8) * Hd + h];
            const float2 bv = *(const float2*)&b2[h];
            float2 o0, o1;
            o0.x = xa.x * xs0 + acc[i][n][0] + w120 * bv.x;
            o0.y = xa.y * xs0 + acc[i][n][1] + w120 * bv.y;
            o1.x = xb.x * xs1 + acc[i][n][2] + w121 * bv.x;
            o1.y = xb.y * xs1 + acc[i][n][3] + w121 * bv.y;
            *(float2*)&out[(size_t)r0 * Hd + h] = o0;
            *(float2*)&out[(size_t)(r0 + 8) * Hd + h] = o1;
        }
    }
}

// ---------------- launch ------------------------------------------------------
extern "C" void kernel_launch(void* const* d_in, const int* in_sizes, int n_in,
                              void* d_out, int out_size) {
    const float* x   = (const float*)d_in[0];
    const int*   dm  = (const int*)d_in[1];
    const float* gw1 = (const float*)d_in[2];
    const float* gb1 = (const float*)d_in[3];
    const float* gw2 = (const float*)d_in[4];
    const float* gb2 = (const float*)d_in[5];
    const float* sb  = (const float*)d_in[6];
    const float* bb  = (const float*)d_in[7];
    const float* si  = (const float*)d_in[8];
    const float* bi  = (const float*)d_in[9];
    const float* aw1 = (const float*)d_in[10];
    const float* ab1 = (const float*)d_in[11];
    const float* aw2 = (const float*)d_in[12];
    const float* ab2 = (const float*)d_in[13];
    float* out = (float*)d_out;

    cudaFuncSetAttribute(k_up, cudaFuncAttributeMaxDynamicSharedMemorySize, UP_SMEM);
    cudaFuncSetAttribute(k_down, cudaFuncAttributeMaxDynamicSharedMemorySize, DN_SMEM);

    k_gate<<<Td / 8, 256>>>(x, dm, gw1, gb1, gw2, gb2);
    k_trans1<<<dim3(Fd / 32, Hd / 32), dim3(32, 8)>>>(aw1, sb, si);
    k_trans2<<<dim3(Hd / 32, Fd / 32), dim3(32, 8)>>>(aw2);
    k_prepc<<<(2 * Fd) / 256, 256>>>(aw1, bb, bi, ab1);
    k_up<<<dim3(Fd / 128, Td / 128), 256, UP_SMEM>>>();
    k_down<<<dim3(Hd / 256, Td / 128), 256, DN_SMEM>>>(x, ab2, out);
}

// round 6
// speedup vs baseline: 3.3129x; 1.0562x over previous
#include <cuda_runtime.h>
#include <cuda_fp16.h>
#include <cstdint>

#define Hd 1024
#define Fd 2048
#define Td 8192

// ---------------- scratch (__device__ globals; no allocs allowed) -------------
__device__ __align__(16) float g_wts[Td * 4];    // w0, w1, w2, w1+w2
__device__ __align__(16) float g_cvec[2][Fd];    // b_d @ ad_w1 + ad_b1
__device__ __align__(16) __half g_xh[(size_t)Td * Hd];   // norm(x) fp16
__device__ __align__(16) __half g_Bb[(size_t)Fd * Hd];   // (W1*s_book)^T fp16
__device__ __align__(16) __half g_Bi[(size_t)Fd * Hd];   // (W1*s_iwslt)^T fp16
__device__ __align__(16) __half g_W2[(size_t)Hd * Fd];   // W2^T fp16
__device__ __align__(16) __half g_g[(size_t)Td * Fd];    // combined activation fp16

// ---------------- PTX helpers -------------------------------------------------
__device__ __forceinline__ uint32_t smem_u32(const void* p) {
    uint32_t a;
    asm("{ .reg .u64 t; cvta.to.shared.u64 t, %1; cvt.u32.u64 %0, t; }"
        : "=r"(a) : "l"(p));
    return a;
}
#define CP16(dst, src) \
    asm volatile("cp.async.cg.shared.global [%0], [%1], 16;" \
                 :: "r"(dst), "l"(__cvta_generic_to_global(src)))
#define CP_COMMIT() asm volatile("cp.async.commit_group;" ::: "memory")
#define CP_WAITG(n) asm volatile("cp.async.wait_group %0;" :: "n"(n) : "memory")
#define LDSM4(r, a) \
    asm volatile("ldmatrix.sync.aligned.m8n8.x4.shared.b16 {%0,%1,%2,%3}, [%4];" \
                 : "=r"((r)[0]), "=r"((r)[1]), "=r"((r)[2]), "=r"((r)[3]) : "r"(a))

__device__ __forceinline__ void mma_f16(float* d, const uint32_t* a,
                                        uint32_t b0, uint32_t b1) {
    asm volatile(
        "mma.sync.aligned.m16n8k16.row.col.f32.f16.f16.f32 "
        "{%0,%1,%2,%3}, {%4,%5,%6,%7}, {%8,%9}, {%0,%1,%2,%3};"
        : "+f"(d[0]), "+f"(d[1]), "+f"(d[2]), "+f"(d[3])
        : "r"(a[0]), "r"(a[1]), "r"(a[2]), "r"(a[3]), "r"(b0), "r"(b1));
}

__device__ __forceinline__ uint32_t hpack(float a, float b) {
    const __half2 h = __floats2half2_rn(a, b);
    return *(const uint32_t*)&h;
}

// ---------------- kernel: LN stats + gate weights + norm(x)->fp16 -------------
__global__ void k_gate(const float* __restrict__ x, const int* __restrict__ dm,
                       const float* __restrict__ gw1, const float* __restrict__ gb1,
                       const float* __restrict__ gw2, const float* __restrict__ gb2) {
    const int t = blockIdx.x * 8 + (threadIdx.x >> 5);
    const int lane = threadIdx.x & 31;
    const float* xr = x + (size_t)t * Hd;

    float4 xv[8];
    float s = 0.f, ss = 0.f, a0 = 0.f, a1 = 0.f, a2 = 0.f, a3 = 0.f;
    #pragma unroll
    for (int it = 0; it < 8; it++) {
        const int h = lane * 4 + it * 128;
        xv[it] = *(const float4*)(xr + h);
        const float4 v = xv[it];
        s  += v.x + v.y + v.z + v.w;
        ss += v.x * v.x + v.y * v.y + v.z * v.z + v.w * v.w;
        const float4* gw = (const float4*)(gw1 + h * 4);
        float4 w0r = gw[0], w1r = gw[1], w2r = gw[2], w3r = gw[3];
        a0 += v.x * w0r.x + v.y * w1r.x + v.z * w2r.x + v.w * w3r.x;
        a1 += v.x * w0r.y + v.y * w1r.y + v.z * w2r.y + v.w * w3r.y;
        a2 += v.x * w0r.z + v.y * w1r.z + v.z * w2r.z + v.w * w3r.z;
        a3 += v.x * w0r.w + v.y * w1r.w + v.z * w2r.w + v.w * w3r.w;
    }
    #pragma unroll
    for (int o = 16; o; o >>= 1) {
        s  += __shfl_xor_sync(0xffffffffu, s, o);
        ss += __shfl_xor_sync(0xffffffffu, ss, o);
        a0 += __shfl_xor_sync(0xffffffffu, a0, o);
        a1 += __shfl_xor_sync(0xffffffffu, a1, o);
        a2 += __shfl_xor_sync(0xffffffffu, a2, o);
        a3 += __shfl_xor_sync(0xffffffffu, a3, o);
    }
    const float mean = s * (1.f / Hd);
    const float var = ss * (1.f / Hd) - mean * mean;
    const float rstd = rsqrtf(var + 1e-6f);

    #pragma unroll
    for (int it = 0; it < 8; it++) {
        const int h = lane * 4 + it * 128;
        const float4 v = xv[it];
        uint2 o;
        o.x = hpack((v.x - mean) * rstd, (v.y - mean) * rstd);
        o.y = hpack((v.z - mean) * rstd, (v.w - mean) * rstd);
        *(uint2*)(g_xh + (size_t)t * Hd + h) = o;
    }

    if (lane == 0) {
        float hv[4] = {fmaxf(a0 + gb1[0], 0.f), fmaxf(a1 + gb1[1], 0.f),
                       fmaxf(a2 + gb1[2], 0.f), fmaxf(a3 + gb1[3], 0.f)};
        float lg[4];
        #pragma unroll
        for (int e = 0; e < 4; e++) {
            float acc = gb2[e];
            #pragma unroll
            for (int d = 0; d < 4; d++) acc += hv[d] * gw2[d * 4 + e];
            if (dm[e] == 0) acc = -1e9f;
            lg[e] = acc;
        }
        const float mx = fmaxf(fmaxf(lg[0], lg[1]), fmaxf(lg[2], lg[3]));
        const float e0 = expf(lg[0] - mx), e1 = expf(lg[1] - mx);
        const float e2 = expf(lg[2] - mx), e3 = expf(lg[3] - mx);
        const float inv = 1.f / (e0 + e1 + e2 + e3);
        g_wts[4 * t + 0] = e0 * inv;
        g_wts[4 * t + 1] = e1 * inv;
        g_wts[4 * t + 2] = e2 * inv;
        g_wts[4 * t + 3] = (e1 + e2) * inv;
    }
}

// ---------------- kernel: transpose + scale W1 -> fp16, both domains ----------
__global__ void k_trans1(const float* __restrict__ w1, const float* __restrict__ sb,
                         const float* __restrict__ si) {
    __shared__ float t[32][33];
    const int tx = threadIdx.x, ty = threadIdx.y;
    const int f0 = blockIdx.x * 32, h0 = blockIdx.y * 32;
    #pragma unroll
    for (int i = 0; i < 4; i++) {
        const int h = h0 + ty + i * 8;
        t[ty + i * 8][tx] = w1[(size_t)h * Fd + f0 + tx];
    }
    __syncthreads();
    const int h = h0 + tx;
    const float s_b = sb[h], s_i = si[h];
    #pragma unroll
    for (int i = 0; i < 4; i++) {
        const int fo = f0 + ty + i * 8;
        const float w = t[tx][ty + i * 8];
        const size_t o = (size_t)fo * Hd + h;
        g_Bb[o] = __float2half_rn(w * s_b);
        g_Bi[o] = __float2half_rn(w * s_i);
    }
}

// ---------------- kernel: transpose W2 -> fp16 --------------------------------
__global__ void k_trans2(const float* __restrict__ w2) {
    __shared__ float t[32][33];
    const int tx = threadIdx.x, ty = threadIdx.y;
    const int h0 = blockIdx.x * 32, f0 = blockIdx.y * 32;
    #pragma unroll
    for (int i = 0; i < 4; i++) {
        const int f = f0 + ty + i * 8;
        t[ty + i * 8][tx] = w2[(size_t)f * Hd + h0 + tx];
    }
    __syncthreads();
    const int f = f0 + tx;
    #pragma unroll
    for (int i = 0; i < 4; i++) {
        const int ho = h0 + ty + i * 8;
        g_W2[(size_t)ho * Fd + f] = __float2half_rn(t[tx][ty + i * 8]);
    }
}

// ---------------- kernel: c_d = b_d @ W1 + ad_b1, split-K parallel ------------
// grid 128 blocks x 256 thr: block covers 32 outputs (i-contig), 8-way K split.
__global__ void k_prepc(const float* __restrict__ w1, const float* __restrict__ bb,
                        const float* __restrict__ bi, const float* __restrict__ ab1) {
    __shared__ float red[8][32];
    const int lane32 = threadIdx.x & 31;
    const int ks = threadIdx.x >> 5;
    const int i = blockIdx.x * 32 + lane32;        // 0..4095
    const int d = i >> 11;
    const int f = i & (Fd - 1);
    const float* bv = d ? bi : bb;
    float acc = 0.f;
    #pragma unroll 8
    for (int h = ks * 128; h < ks * 128 + 128; h++)
        acc = fmaf(__ldg(bv + h), w1[(size_t)h * Fd + f], acc);
    red[ks][lane32] = acc;
    __syncthreads();
    if (ks == 0) {
        float s = red[0][lane32];
        #pragma unroll
        for (int q = 1; q < 8; q++) s += red[q][lane32];
        g_cvec[d][f] = ab1[f] + s;
    }
}

// ---------------- kernel: up GEMM, 512 thr / 16 warps, fused gate-combine -----
// CTA 128m x 128f per domain. dom = wid>>3; within: 4m x 2n, warp 32m x 64f.
// Stage (24KB): A 128x32 (8K) | B_book 128x32 (8K) | B_iwslt 128x32 (8K); x4.
#define UP_SMEM  98304
#define UP_STAGE 24576
__global__ void __launch_bounds__(512, 1) k_up() {
    extern __shared__ char smem[];
    const uint32_t sm = smem_u32(smem);
    const int tid = threadIdx.x, lane = tid & 31, wid = tid >> 5;
    const int m0 = blockIdx.y * 128, n0 = blockIdx.x * 128;
    const int dom = wid >> 3, w8 = wid & 7;
    const int mw = (w8 & 3) * 32, nw = (w8 >> 2) * 64;
    const int aRow = lane & 15, aK = lane >> 4;
    const int bRow = (lane & 7) + ((lane >> 4) << 3), bK = (lane >> 3) & 1;
    const __half* Bsrc[2] = {g_Bb, g_Bi};

    float acc[2][8][4];
    #pragma unroll
    for (int i = 0; i < 2; i++)
        #pragma unroll
        for (int n = 0; n < 8; n++)
            #pragma unroll
            for (int q = 0; q < 4; q++) acc[i][n][q] = 0.f;

    auto load = [&](int c) {
        const uint32_t sb = sm + (c & 3) * UP_STAGE;
        {   // A: 512 x 16B units, kb = tid>>7, r = tid&127
            const int r = tid & 127, kb = tid >> 7;
            CP16(sb + tid * 16, g_xh + (size_t)(m0 + r) * Hd + c * 32 + kb * 8);
        }
        #pragma unroll
        for (int rep = 0; rep < 2; rep++) {   // B: 1024 units (2 domains)
            const int u = tid + rep * 512;
            const int d = u >> 9, within = u & 511;
            const int f = within & 127, kb = within >> 7;
            CP16(sb + 8192 + d * 8192 + within * 16,
                 Bsrc[d] + (size_t)(n0 + f) * Hd + c * 32 + kb * 8);
        }
        CP_COMMIT();
    };

    load(0); load(1); load(2);

    #pragma unroll 1
    for (int c = 0; c < 32; c++) {
        if (c < 29) CP_WAITG(2); else CP_WAITG(0);
        __syncthreads();
        if (c + 3 < 32) load(c + 3);
        const uint32_t smA = sm + (c & 3) * UP_STAGE;
        const uint32_t smB = smA + 8192 + dom * 8192;
        #pragma unroll
        for (int j = 0; j < 2; j++) {
            uint32_t a[2][4];
            const uint32_t aBase = smA + (((2 * j + aK) << 7) + mw + aRow) * 16;
            #pragma unroll
            for (int i = 0; i < 2; i++) LDSM4(a[i], aBase + i * 256);
            uint32_t b[4][4];
            const uint32_t bBase = smB + (((2 * j + bK) << 7) + nw + bRow) * 16;
            #pragma unroll
            for (int nb = 0; nb < 4; nb++) LDSM4(b[nb], bBase + nb * 256);
            #pragma unroll
            for (int i = 0; i < 2; i++)
                #pragma unroll
                for (int nb = 0; nb < 4; nb++) {
                    mma_f16(acc[i][2 * nb + 0], a[i], b[nb][0], b[nb][1]);
                    mma_f16(acc[i][2 * nb + 1], a[i], b[nb][2], b[nb][3]);
                }
        }
    }

    // --- epilogue: dom1 -> smem (w2*relu), dom0 combines, writes g fp16 -------
    __syncthreads();
    const int g = lane >> 2, tq = lane & 3;
    float* ex = (float*)smem;               // [128][132]
    if (dom == 1) {
        #pragma unroll
        for (int i = 0; i < 2; i++) {
            const int r = mw + 16 * i + g;
            const float w2a = g_wts[4 * (m0 + r) + 2];
            const float w2b = g_wts[4 * (m0 + r + 8) + 2];
            #pragma unroll
            for (int n = 0; n < 8; n++) {
                const int col = nw + 8 * n + 2 * tq;
                const float cv0 = g_cvec[1][n0 + col], cv1 = g_cvec[1][n0 + col + 1];
                float2 v0, v1;
                v0.x = w2a * fmaxf(acc[i][n][0] + cv0, 0.f);
                v0.y = w2a * fmaxf(acc[i][n][1] + cv1, 0.f);
                v1.x = w2b * fmaxf(acc[i][n][2] + cv0, 0.f);
                v1.y = w2b * fmaxf(acc[i][n][3] + cv1, 0.f);
                *(float2*)(ex + (size_t)r * 132 + col) = v0;
                *(float2*)(ex + (size_t)(r + 8) * 132 + col) = v1;
            }
        }
    }
    __syncthreads();
    if (dom == 0) {
        #pragma unroll
        for (int i = 0; i < 2; i++) {
            const int r = mw + 16 * i + g;
            const float w1a = g_wts[4 * (m0 + r) + 1];
            const float w1b = g_wts[4 * (m0 + r + 8) + 1];
            #pragma unroll
            for (int n = 0; n < 8; n++) {
                const int col = nw + 8 * n + 2 * tq;
                const float cv0 = g_cvec[0][n0 + col], cv1 = g_cvec[0][n0 + col + 1];
                const float2 s0 = *(const float2*)(ex + (size_t)r * 132 + col);
                const float2 s1 = *(const float2*)(ex + (size_t)(r + 8) * 132 + col);
                const float g0 = w1a * fmaxf(acc[i][n][0] + cv0, 0.f) + s0.x;
                const float g1 = w1a * fmaxf(acc[i][n][1] + cv1, 0.f) + s0.y;
                const float g2 = w1b * fmaxf(acc[i][n][2] + cv0, 0.f) + s1.x;
                const float g3 = w1b * fmaxf(acc[i][n][3] + cv1, 0.f) + s1.y;
                *(uint32_t*)(g_g + (size_t)(m0 + r) * Fd + n0 + col) = hpack(g0, g1);
                *(uint32_t*)(g_g + (size_t)(m0 + r + 8) * Fd + n0 + col) = hpack(g2, g3);
            }
        }
    }
}

// ---------------- kernel: down GEMM + residual + gated mix (unchanged ctrl) ---
// CTA 128m x 256h. 8 warps 2m x 4n, warp 64x64.
#define DN_SMEM  98304
#define DN_STAGE 24576
__global__ void __launch_bounds__(256, 1) k_down(const float* __restrict__ x,
                                                 const float* __restrict__ b2,
                                                 float* __restrict__ out) {
    extern __shared__ char smem[];
    const uint32_t sm = smem_u32(smem);
    const int tid = threadIdx.x, lane = tid & 31, wid = tid >> 5;
    const int m0 = blockIdx.y * 128, n0 = blockIdx.x * 256;
    const int mw = (wid & 1) * 64, nw = (wid >> 1) * 64;
    const int aRow = lane & 15, aK = lane >> 4;
    const int bRow = (lane & 7) + ((lane >> 4) << 3), bK = (lane >> 3) & 1;

    float acc[4][8][4];
    #pragma unroll
    for (int i = 0; i < 4; i++)
        #pragma unroll
        for (int n = 0; n < 8; n++)
            #pragma unroll
            for (int q = 0; q < 4; q++) acc[i][n][q] = 0.f;

    auto load = [&](int c) {
        const uint32_t sb = sm + (c & 3) * DN_STAGE;
        #pragma unroll
        for (int rep = 0; rep < 2; rep++) {
            const int idx = tid + rep * 256;
            const int r = idx & 127, kb = idx >> 7;
            CP16(sb + idx * 16, g_g + (size_t)(m0 + r) * Fd + c * 32 + kb * 8);
        }
        #pragma unroll
        for (int rep = 0; rep < 4; rep++) {
            const int u = tid + rep * 256;
            const int h = u & 255, kb = u >> 8;
            CP16(sb + 8192 + u * 16, g_W2 + (size_t)(n0 + h) * Fd + c * 32 + kb * 8);
        }
        CP_COMMIT();
    };

    load(0); load(1); load(2);

    #pragma unroll 1
    for (int c = 0; c < 64; c++) {
        if (c < 61) CP_WAITG(2); else CP_WAITG(0);
        __syncthreads();
        if (c + 3 < 64) load(c + 3);
        const uint32_t smA = sm + (c & 3) * DN_STAGE;
        const uint32_t smB = smA + 8192;
        #pragma unroll
        for (int j = 0; j < 2; j++) {
            uint32_t a[4][4];
            const uint32_t aBase = smA + (((2 * j + aK) << 7) + mw + aRow) * 16;
            #pragma unroll
            for (int i = 0; i < 4; i++) LDSM4(a[i], aBase + i * 256);
            uint32_t b[4][4];
            const uint32_t bBase = smB + (((2 * j + bK) << 8) + nw + bRow) * 16;
            #pragma unroll
            for (int nb = 0; nb < 4; nb++) LDSM4(b[nb], bBase + nb * 256);
            #pragma unroll
            for (int i = 0; i < 4; i++)
                #pragma unroll
                for (int nb = 0; nb < 4; nb++) {
                    mma_f16(acc[i][2 * nb + 0], a[i], b[nb][0], b[nb][1]);
                    mma_f16(acc[i][2 * nb + 1], a[i], b[nb][2], b[nb][3]);
                }
        }
    }

    const int g = lane >> 2, tq = lane & 3;
    #pragma unroll
    for (int i = 0; i < 4; i++) {
        const int r0 = m0 + mw + 16 * i + g;
        const float4 wv0 = *(const float4*)&g_wts[4 * r0];
        const float4 wv1 = *(const float4*)&g_wts[4 * (r0 + 8)];
        const float xs0 = 1.f + wv0.x, w120 = wv0.w;
        const float xs1 = 1.f + wv1.x, w121 = wv1.w;
        #pragma unroll
        for (int n = 0; n < 8; n++) {
            const int h = n0 + nw + 8 * n + 2 * tq;
            const float2 xa = *(const float2*)&x[(size_t)r0 * Hd + h];
            const float2 xb = *(const float2*)&x[(size_t)(r0 + 8) * Hd + h];
            const float2 bv = *(const float2*)&b2[h];
            float2 o0, o1;
            o0.x = xa.x * xs0 + acc[i][n][0] + w120 * bv.x;
            o0.y = xa.y * xs0 + acc[i][n][1] + w120 * bv.y;
            o1.x = xb.x * xs1 + acc[i][n][2] + w121 * bv.x;
            o1.y = xb.y * xs1 + acc[i][n][3] + w121 * bv.y;
            *(float2*)&out[(size_t)r0 * Hd + h] = o0;
            *(float2*)&out[(size_t)(r0 + 8) * Hd + h] = o1;
        }
    }
}

// ---------------- launch (order chosen so slot #4 = k_up for ncu) -------------
extern "C" void kernel_launch(void* const* d_in, const int* in_sizes, int n_in,
                              void* d_out, int out_size) {
    const float* x   = (const float*)d_in[0];
    const int*   dm  = (const int*)d_in[1];
    const float* gw1 = (const float*)d_in[2];
    const float* gb1 = (const float*)d_in[3];
    const float* gw2 = (const float*)d_in[4];
    const float* gb2 = (const float*)d_in[5];
    const float* sb  = (const float*)d_in[6];
    const float* bb  = (const float*)d_in[7];
    const float* si  = (const float*)d_in[8];
    const float* bi  = (const float*)d_in[9];
    const float* aw1 = (const float*)d_in[10];
    const float* ab1 = (const float*)d_in[11];
    const float* aw2 = (const float*)d_in[12];
    const float* ab2 = (const float*)d_in[13];
    float* out = (float*)d_out;

    cudaFuncSetAttribute(k_up, cudaFuncAttributeMaxDynamicSharedMemorySize, UP_SMEM);
    cudaFuncSetAttribute(k_down, cudaFuncAttributeMaxDynamicSharedMemorySize, DN_SMEM);

    k_trans1<<<dim3(Fd / 32, Hd / 32), dim3(32, 8)>>>(aw1, sb, si);   // #1
    k_prepc<<<(2 * Fd) / 32, 256>>>(aw1, bb, bi, ab1);                // #2
    k_gate<<<Td / 8, 256>>>(x, dm, gw1, gb1, gw2, gb2);               // #3
    k_up<<<dim3(Fd / 128, Td / 128), 512, UP_SMEM>>>();               // #4 (ncu)
    k_trans2<<<dim3(Hd / 32, Fd / 32), dim3(32, 8)>>>(aw2);           // #5
    k_down<<<dim3(Hd / 256, Td / 128), 256, DN_SMEM>>>(x, ab2, out);  // #6
}